// round 1
// baseline (speedup 1.0000x reference)
#include <cuda_runtime.h>
#include <math.h>

#define NC   19      // classes
#define DD   256     // embedding dim
#define HW   16384   // 128*128
#define NB   8       // batch
#define PX   128     // pixels per tile
#define NTILE 1024   // NB*HW/PX
#define NBLK 152     // persistent blocks (1 per SM on GB300)
#define TPB  256
#define TSTRIDE 257  // padded tile row stride (floats)

// -------- device scratch (no allocations allowed) --------
__device__ float g_PS[NBLK * NC * DD];   // per-block partial class sums
__device__ float g_PN[NBLK * NC * DD];   // per-block partial normalized sums
__device__ float g_PC[NBLK * NC];        // per-block partial counts
__device__ float g_sums[NC * DD];
__device__ float g_nsums[NC * DD];
__device__ float g_cnt[NC];

// smem layout (floats):
//   tile   : PX*TSTRIDE          (32896)
//   accS   : NC*DD               (4864)
//   accN   : NC*DD               (4864)
//   rinv   : PX                  (128)
//   nh     : 2*PX                (256)
//   cntb   : NC (+1 pad)         (20)
// ints after that:
//   lab    : PX (128), cnt_t: 20, starts: 20
#define SMEM_FLOATS (PX*TSTRIDE + 2*NC*DD + PX + 2*PX + 20)
#define SMEM_INTS   (PX + 20 + 20)
#define SMEM_BYTES  ((SMEM_FLOATS + SMEM_INTS) * 4)

__global__ __launch_bounds__(TPB, 1)
void fse_pass1(const float* __restrict__ in, const int* __restrict__ tgt)
{
    extern __shared__ float sm[];
    float* tile = sm;
    float* accS = tile + PX * TSTRIDE;
    float* accN = accS + NC * DD;
    float* rinv = accN + NC * DD;
    float* nh   = rinv + PX;
    float* cntb = nh + 2 * PX;
    int*   lab    = (int*)(cntb + 20);
    int*   cnt_t  = lab + PX;
    int*   starts = cnt_t + 20;

    const int tid  = threadIdx.x;
    const int lane = tid & 31;
    const int drow = tid >> 5;          // warp id 0..7

    // zero block accumulators
    for (int i = tid; i < NC * DD; i += TPB) { accS[i] = 0.f; accN[i] = 0.f; }
    if (tid < NC) cntb[tid] = 0.f;
    __syncthreads();

    for (int t = blockIdx.x; t < NTILE; t += gridDim.x) {
        const int b   = t >> 7;
        const int hw0 = (t & 127) << 7;
        const float* src = in + ((size_t)b * DD) * HW + hw0;

        // ---- stage tile: tile[p][d], coalesced global reads, conflict-free STS ----
        #pragma unroll 4
        for (int it = 0; it < 32; ++it) {
            const int d = (drow << 5) + it;
            const float* row = src + (size_t)d * HW;
            float v0 = row[lane];
            float v1 = row[lane + 32];
            float v2 = row[lane + 64];
            float v3 = row[lane + 96];
            float* tb = tile + d;
            tb[(lane      ) * TSTRIDE] = v0;
            tb[(lane + 32 ) * TSTRIDE] = v1;
            tb[(lane + 64 ) * TSTRIDE] = v2;
            tb[(lane + 96 ) * TSTRIDE] = v3;
        }
        if (tid < 20) cnt_t[tid] = 0;
        if (tid < PX) lab[tid] = tgt[b * HW + hw0 + tid];
        __syncthreads();

        // ---- per-pixel ||feat||^2 (2 threads per pixel) ----
        {
            const int p = tid & 127, h = tid >> 7;
            const float* rp = tile + p * TSTRIDE + h * 128;
            float s0 = 0.f, s1 = 0.f;
            #pragma unroll 8
            for (int i = 0; i < 128; i += 2) {
                float a = rp[i], c = rp[i + 1];
                s0 += a * a; s1 += c * c;
            }
            nh[h * 128 + p] = s0 + s1;
        }
        // ---- histogram of labels ----
        if (tid < PX) atomicAdd(&cnt_t[lab[tid]], 1);
        __syncthreads();

        if (tid == 0) {
            int acc = 0;
            #pragma unroll
            for (int c = 0; c < NC; ++c) { starts[c] = acc; acc += cnt_t[c]; }
            starts[NC] = acc;
        }
        __syncthreads();

        // ---- deterministic counting-sort scatter + rinv ----
        if (tid < PX) {
            rinv[tid] = rsqrtf(nh[tid] + nh[128 + tid]);
            const int myl = lab[tid];
            int r = 0;
            for (int q = 0; q < tid; ++q) r += (lab[q] == myl);
            // reuse nh[] as order buffer (ints stored via int view)
            ((int*)nh)[starts[myl] + r] = tid;
        }
        if (tid < NC) cntb[tid] += (float)cnt_t[tid];
        __syncthreads();

        // ---- accumulate: each thread owns one d (=tid), register acc per class ----
        const int* order = (const int*)nh;
        for (int c = 0; c < NC; ++c) {
            const int s0 = starts[c], e0 = starts[c + 1];
            float aS = 0.f, aN = 0.f;
            for (int k = s0; k < e0; ++k) {
                const int p = order[k];
                const float r = rinv[p];
                const float v = tile[p * TSTRIDE + tid];
                aS += v;
                aN += v * r;
            }
            accS[c * DD + tid] += aS;
            accN[c * DD + tid] += aN;
        }
        __syncthreads();
    }

    // ---- flush per-block partials ----
    const int base = blockIdx.x * (NC * DD);
    for (int i = tid; i < NC * DD; i += TPB) {
        g_PS[base + i] = accS[i];
        g_PN[base + i] = accN[i];
    }
    if (tid < NC) g_PC[blockIdx.x * NC + tid] = cntb[tid];
}

__global__ void fse_reduce()
{
    const int j = blockIdx.x * blockDim.x + threadIdx.x;
    if (j < NC * DD) {
        float s = 0.f;
        for (int b = 0; b < NBLK; ++b) s += g_PS[b * NC * DD + j];
        g_sums[j] = s;
    } else if (j < 2 * NC * DD) {
        const int jj = j - NC * DD;
        float s = 0.f;
        for (int b = 0; b < NBLK; ++b) s += g_PN[b * NC * DD + jj];
        g_nsums[jj] = s;
    } else if (j < 2 * NC * DD + NC) {
        const int jj = j - 2 * NC * DD;
        float s = 0.f;
        for (int b = 0; b < NBLK; ++b) s += g_PC[b * NC + jj];
        g_cnt[jj] = s;
    }
}

__global__ void fse_final(float* __restrict__ out)
{
    __shared__ float cen[NC * DD];
    __shared__ float ncn[NC], nsd[NC], cnt_s[NC], pl[NC];
    __shared__ float pp[NC * NC];
    const int tid = threadIdx.x;

    if (tid < NC) cnt_s[tid] = g_cnt[tid];
    __syncthreads();
    for (int i = tid; i < NC * DD; i += 256) {
        const int c = i >> 8;
        cen[i] = g_sums[i] / fmaxf(cnt_s[c], 1.f);
    }
    __syncthreads();
    if (tid < NC) {
        float n2 = 0.f, dd = 0.f;
        for (int d = 0; d < DD; ++d) {
            const float cv = cen[tid * DD + d];
            n2 += cv * cv;
            dd += cv * g_nsums[tid * DD + d];
        }
        ncn[tid] = sqrtf(n2);
        nsd[tid] = dd;
    }
    __syncthreads();
    for (int pr = tid; pr < NC * NC; pr += 256) {
        const int i = pr / NC, j = pr - i * NC;
        float g = 0.f;
        for (int d = 0; d < DD; ++d) g += cen[i * DD + d] * cen[j * DD + d];
        const float S = g / fmaxf(ncn[i] * ncn[j], 1e-8f);
        pp[pr] = (i == j) ? (1.f - S) : fmaxf(S, 0.f);
    }
    __syncthreads();
    if (tid < NC) {
        float v = 0.f;
        if (cnt_s[tid] > 0.f) {
            float m = 0.f;
            for (int j = 0; j < NC; ++j) m += pp[tid * NC + j];
            m /= (float)NC;                                    // diff per-class
            const float simc = 1.f - nsd[tid] / (ncn[tid] * cnt_s[tid]);
            v = m + simc;
        }
        pl[tid] = v;
    }
    __syncthreads();
    if (tid == 0) {
        float tot = 0.f;
        for (int i = 0; i < NC; ++i) tot += pl[i];
        out[0] = tot;
    }
}

extern "C" void kernel_launch(void* const* d_in, const int* in_sizes, int n_in,
                              void* d_out, int out_size)
{
    const float* in  = (const float*)d_in[0];
    const int*   tgt = (const int*)d_in[1];
    float*       out = (float*)d_out;

    cudaFuncSetAttribute(fse_pass1, cudaFuncAttributeMaxDynamicSharedMemorySize, SMEM_BYTES);

    fse_pass1<<<NBLK, TPB, SMEM_BYTES>>>(in, tgt);
    const int total2 = 2 * NC * DD + NC;
    fse_reduce<<<(total2 + 255) / 256, 256>>>();
    fse_final<<<1, 256>>>(out);
}